// round 5
// baseline (speedup 1.0000x reference)
#include <cuda_runtime.h>
#include <math.h>
#include <stdint.h>

#define B_   32
#define S_   64
#define E_   512
#define H_   1024
#define V_   32000
#define G3H  (3 * H_)
#define NTOK (B_ * S_)
#define BH   (B_ * H_)

typedef unsigned long long ull;

// ---------------- scratch (device globals; no allocation allowed) ----------------
__device__ float g_ex[NTOK * E_];
__device__ float g_dx[NTOK * E_];
__device__ float g_xgA[NTOK * G3H];
__device__ float g_xgB[NTOK * G3H];
__device__ float g_seqA[NTOK * H_];
__device__ float g_seqB[NTOK * H_];
__device__ float g_h[8][BH];

// ---------------- embedding gather ----------------
__global__ void embed_kernel(const int* __restrict__ idx,
                             const float* __restrict__ emb,
                             float* __restrict__ out) {
    int tok = blockIdx.x;
    int row = idx[tok];
    const float4* src = (const float4*)(emb + (size_t)row * E_);
    float4* dst = (float4*)(out + (size_t)tok * E_);
    for (int i = threadIdx.x; i < E_ / 4; i += blockDim.x) dst[i] = src[i];
}

// ---------------- packed f32x2 FMA (Blackwell FFMA2 — ptxas never auto-emits) ----------------
__device__ __forceinline__ ull fma2(ull a, ull b, ull c) {
    ull d;
    asm("fma.rn.f32x2 %0, %1, %2, %3;" : "=l"(d) : "l"(a), "l"(b), "l"(c));
    return d;
}

// ---------------- f32x2 SGEMM: C[M,N] = A[M,K]*W[N,K]^T + bias[N] ----------------
// 128x128 tile, BK=8, 256 threads, 8x8 per thread; accumulators are m-packed f32x2
// pairs; W tile duplicated in smem so b-pairs (w,w) load directly. ~110 regs -> 2 CTA/SM.
// Requires M%128==0, N%128==0, K%8==0.
#define BM 128
#define BN 128
#define BK 8

__global__ __launch_bounds__(256)
void sgemm_f32x2_kernel(const float* __restrict__ A,
                        const float* __restrict__ W,
                        const float* __restrict__ bias,
                        float* __restrict__ C,
                        int M, int N, int K) {
    __shared__ float As[BK][BM];         // [k][m]
    __shared__ float Ws2[BK][2 * BN];    // [k][2n] duplicated pairs

    const int tid  = threadIdx.x;
    const int lane = tid & 31;
    const int warp = tid >> 5;
    const int lm = lane & 7;             // 8 m-slots
    const int ln = lane >> 3;            // 4 n-slots
    const int wm = (warp >> 2) * 64;     // warp m offset (2 warps over m)
    const int wn = (warp & 3) * 32;      // warp n offset (4 warps over n)

    const int bm = blockIdx.x * BM;
    const int bn = blockIdx.y * BN;

    const int lrow = tid & 127;          // staging row
    const int kq   = (tid >> 7) * 4;     // staging k quad: 0 or 4

    const float* Ag = A + (size_t)(bm + lrow) * K + kq;
    const float* Wg = W + (size_t)(bn + lrow) * K + kq;

    ull acc[4][8];
#pragma unroll
    for (int i = 0; i < 4; i++)
#pragma unroll
        for (int j = 0; j < 8; j++) acc[i][j] = 0ull;

    // prefetch tile 0
    float4 av = *(const float4*)(Ag);
    float4 wv = *(const float4*)(Wg);

    for (int k0 = 0; k0 < K; k0 += BK) {
        __syncthreads();   // previous tile's reads done
        As[kq + 0][lrow] = av.x;
        As[kq + 1][lrow] = av.y;
        As[kq + 2][lrow] = av.z;
        As[kq + 3][lrow] = av.w;
        *(float2*)&Ws2[kq + 0][2 * lrow] = make_float2(wv.x, wv.x);
        *(float2*)&Ws2[kq + 1][2 * lrow] = make_float2(wv.y, wv.y);
        *(float2*)&Ws2[kq + 2][2 * lrow] = make_float2(wv.z, wv.z);
        *(float2*)&Ws2[kq + 3][2 * lrow] = make_float2(wv.w, wv.w);
        __syncthreads();

        // prefetch next tile (latency overlapped with compute below)
        if (k0 + BK < K) {
            av = *(const float4*)(Ag + k0 + BK);
            wv = *(const float4*)(Wg + k0 + BK);
        }

#pragma unroll
        for (int k = 0; k < BK; k++) {
            // a: 4 m-pairs (consecutive m), conflict-free LDS.128
            ulonglong2 a0 = *(const ulonglong2*)&As[k][wm + lm * 4];
            ulonglong2 a1 = *(const ulonglong2*)&As[k][wm + 32 + lm * 4];
            // b: 8 duplicated n-pairs, conflict-free (4 distinct banks + broadcast)
            ulonglong2 b0 = *(const ulonglong2*)&Ws2[k][2 * (wn + ln * 4)];
            ulonglong2 b1 = *(const ulonglong2*)&Ws2[k][2 * (wn + ln * 4) + 4];
            ulonglong2 b2 = *(const ulonglong2*)&Ws2[k][2 * (wn + 16 + ln * 4)];
            ulonglong2 b3 = *(const ulonglong2*)&Ws2[k][2 * (wn + 16 + ln * 4) + 4];
            ull ap[4] = {a0.x, a0.y, a1.x, a1.y};
            ull bp[8] = {b0.x, b0.y, b1.x, b1.y, b2.x, b2.y, b3.x, b3.y};
#pragma unroll
            for (int mp = 0; mp < 4; mp++)
#pragma unroll
                for (int j = 0; j < 8; j++)
                    acc[mp][j] = fma2(ap[mp], bp[j], acc[mp][j]);
        }
    }

    // epilogue: unpack pairs, add bias, store two rows per m-pair
    union cvu { ull u; float2 f; };
#pragma unroll
    for (int mp = 0; mp < 4; mp++) {
        int m = bm + wm + lm * 4 + (mp >> 1) * 32 + (mp & 1) * 2;
#pragma unroll
        for (int g = 0; g < 2; g++) {
            int n = bn + wn + g * 16 + ln * 4;
            float4 bv = *(const float4*)(bias + n);
            cvu c0, c1, c2, c3;
            c0.u = acc[mp][g * 4 + 0];
            c1.u = acc[mp][g * 4 + 1];
            c2.u = acc[mp][g * 4 + 2];
            c3.u = acc[mp][g * 4 + 3];
            float4 o0, o1;
            o0.x = c0.f.x + bv.x; o1.x = c0.f.y + bv.x;
            o0.y = c1.f.x + bv.y; o1.y = c1.f.y + bv.y;
            o0.z = c2.f.x + bv.z; o1.z = c2.f.y + bv.z;
            o0.w = c3.f.x + bv.w; o1.w = c3.f.y + bv.w;
            *(float4*)(C + (size_t)m * N + n)       = o0;
            *(float4*)(C + (size_t)(m + 1) * N + n) = o1;
        }
    }
}

// ---------------- fused GRU time step (body shared by single & dual) ----------------
__device__ __forceinline__ void gru_step_body(
        const float* __restrict__ h_prev,
        const float* __restrict__ Whh,
        const float* __restrict__ bhh,
        const float* __restrict__ xg,
        int t, int zero_init, int jblk,
        float* __restrict__ h_next,
        float* __restrict__ y,
        float* h_s) {
    const int tid = threadIdx.x;
    const int b = tid & 31;
    const int j = (jblk << 3) + (tid >> 5);

    float accr = bhh[j];
    float accz = bhh[H_ + j];
    float accn = bhh[2 * H_ + j];
    float h_old = 0.f;

    if (!zero_init) {
        for (int i4 = tid; i4 < BH / 4; i4 += 256) {
            int lin = i4 * 4;
            int bb = lin >> 10;
            int kk = lin & (H_ - 1);
            float4 v = *(const float4*)(h_prev + lin);
            h_s[(kk + 0) * B_ + bb] = v.x;
            h_s[(kk + 1) * B_ + bb] = v.y;
            h_s[(kk + 2) * B_ + bb] = v.z;
            h_s[(kk + 3) * B_ + bb] = v.w;
        }
        __syncthreads();

        const float* wr = Whh + (size_t)j * H_;
        const float* wz = Whh + (size_t)(H_ + j) * H_;
        const float* wn = Whh + (size_t)(2 * H_ + j) * H_;

#pragma unroll 8
        for (int k = 0; k < H_; k += 4) {
            float4 r4 = __ldg((const float4*)(wr + k));
            float4 z4 = __ldg((const float4*)(wz + k));
            float4 n4 = __ldg((const float4*)(wn + k));
            float h0 = h_s[(k + 0) * B_ + b];
            float h1 = h_s[(k + 1) * B_ + b];
            float h2 = h_s[(k + 2) * B_ + b];
            float h3 = h_s[(k + 3) * B_ + b];
            accr += h0 * r4.x + h1 * r4.y + h2 * r4.z + h3 * r4.w;
            accz += h0 * z4.x + h1 * z4.y + h2 * z4.z + h3 * z4.w;
            accn += h0 * n4.x + h1 * n4.y + h2 * n4.z + h3 * n4.w;
        }
        h_old = h_s[j * B_ + b];
    }

    const float* xp = xg + ((size_t)b * S_ + t) * G3H;
    float r = 1.f / (1.f + expf(-(xp[j] + accr)));
    float z = 1.f / (1.f + expf(-(xp[H_ + j] + accz)));
    float n = tanhf(xp[2 * H_ + j] + r * accn);
    float hnew = (1.f - z) * n + z * h_old;

    h_next[b * H_ + j] = hnew;
    if (y) y[((size_t)b * S_ + t) * H_ + j] = hnew;
}

__global__ __launch_bounds__(256)
void gru_step_kernel(const float* __restrict__ h_prev,
                     const float* __restrict__ Whh,
                     const float* __restrict__ bhh,
                     const float* __restrict__ xg,
                     int t, int zero_init,
                     float* __restrict__ h_next,
                     float* __restrict__ y) {
    extern __shared__ float h_s[];
    gru_step_body(h_prev, Whh, bhh, xg, t, zero_init, blockIdx.x, h_next, y, h_s);
}

__global__ __launch_bounds__(256)
void gru_step_dual_kernel(const float* hA, const float* WA, const float* bA,
                          const float* xA, int ziA, float* hnA, float* yA,
                          const float* hB, const float* WB, const float* bB,
                          const float* xB, int ziB, float* hnB, float* yB,
                          int t) {
    extern __shared__ float h_s[];
    if (blockIdx.x < 128)
        gru_step_body(hA, WA, bA, xA, t, ziA, blockIdx.x, hnA, yA, h_s);
    else
        gru_step_body(hB, WB, bB, xB, t, ziB, blockIdx.x - 128, hnB, yB, h_s);
}

// ---------------- driver ----------------
static void run_scan(const float* Whh, const float* bhh, const float* xg,
                     float* hpair, const float* h_init, int zero0, float* yout) {
    for (int t = 0; t < S_; t++) {
        const float* hin;
        int zi = 0;
        if (t == 0) {
            if (zero0) { hin = hpair; zi = 1; }
            else       { hin = h_init; }
        } else {
            hin = hpair + (t & 1) * BH;
        }
        float* hout = hpair + ((t + 1) & 1) * BH;
        gru_step_kernel<<<128, 256, 131072>>>(hin, Whh, bhh, xg, t, zi, hout, yout);
    }
}

extern "C" void kernel_launch(void* const* d_in, const int* in_sizes, int n_in,
                              void* d_out, int out_size) {
    const int*   enc_X   = (const int*)d_in[0];
    const int*   dec_X   = (const int*)d_in[1];
    const float* emb_enc = (const float*)d_in[2];
    const float* emb_dec = (const float*)d_in[3];
    const float* eW0i = (const float*)d_in[4];
    const float* eW0h = (const float*)d_in[5];
    const float* eb0i = (const float*)d_in[6];
    const float* eb0h = (const float*)d_in[7];
    const float* eW1i = (const float*)d_in[8];
    const float* eW1h = (const float*)d_in[9];
    const float* eb1i = (const float*)d_in[10];
    const float* eb1h = (const float*)d_in[11];
    const float* dW0i = (const float*)d_in[12];
    const float* dW0h = (const float*)d_in[13];
    const float* db0i = (const float*)d_in[14];
    const float* db0h = (const float*)d_in[15];
    const float* dW1i = (const float*)d_in[16];
    const float* dW1h = (const float*)d_in[17];
    const float* db1i = (const float*)d_in[18];
    const float* db1h = (const float*)d_in[19];
    const float* fcW  = (const float*)d_in[20];
    const float* fcb  = (const float*)d_in[21];
    float* out = (float*)d_out;

    float *ex, *dx, *xgA, *xgB, *seqA, *seqB, *hb;
    cudaGetSymbolAddress((void**)&ex,   g_ex);
    cudaGetSymbolAddress((void**)&dx,   g_dx);
    cudaGetSymbolAddress((void**)&xgA,  g_xgA);
    cudaGetSymbolAddress((void**)&xgB,  g_xgB);
    cudaGetSymbolAddress((void**)&seqA, g_seqA);
    cudaGetSymbolAddress((void**)&seqB, g_seqB);
    cudaGetSymbolAddress((void**)&hb,   g_h);

    cudaFuncSetAttribute(gru_step_kernel,
                         cudaFuncAttributeMaxDynamicSharedMemorySize, 131072);
    cudaFuncSetAttribute(gru_step_dual_kernel,
                         cudaFuncAttributeMaxDynamicSharedMemorySize, 131072);

    // embeddings
    embed_kernel<<<NTOK, 128>>>(enc_X, emb_enc, ex);
    embed_kernel<<<NTOK, 128>>>(dec_X, emb_dec, dx);

    dim3 g3h(NTOK / BM, G3H / BN);   // M tiles fastest -> W-slice reuse per wave

    // encoder layer 0
    sgemm_f32x2_kernel<<<g3h, 256>>>(ex, eW0i, eb0i, xgA, NTOK, G3H, E_);
    run_scan(eW0h, eb0h, xgA, hb + 0 * 2 * BH, nullptr, 1, seqA);

    // enc layer 1 xg and dec layer 0 xg — both ready now
    sgemm_f32x2_kernel<<<g3h, 256>>>(seqA, eW1i, eb1i, xgA, NTOK, G3H, H_);
    sgemm_f32x2_kernel<<<g3h, 256>>>(dx,   dW0i, db0i, xgB, NTOK, G3H, E_);

    // dual scan: enc layer 1 (zero init, no y) || dec layer 0 (init h_enc0, y->seqA)
    {
        float* hpA = hb + 1 * 2 * BH;
        float* hpB = hb + 2 * 2 * BH;
        const float* h0B = hb + 0 * 2 * BH;
        for (int t = 0; t < S_; t++) {
            const float* hinA; int ziA = 0;
            const float* hinB; int ziB = 0;
            if (t == 0) { hinA = hpA; ziA = 1; hinB = h0B; }
            else        { hinA = hpA + (t & 1) * BH; hinB = hpB + (t & 1) * BH; }
            float* houtA = hpA + ((t + 1) & 1) * BH;
            float* houtB = hpB + ((t + 1) & 1) * BH;
            gru_step_dual_kernel<<<256, 256, 131072>>>(
                hinA, eW1h, eb1h, xgA, ziA, houtA, nullptr,
                hinB, dW0h, db0h, xgB, ziB, houtB, seqA, t);
        }
    }

    // decoder layer 1 (init = enc layer1 final hidden), y -> seqB
    sgemm_f32x2_kernel<<<g3h, 256>>>(seqA, dW1i, db1i, xgA, NTOK, G3H, H_);
    run_scan(dW1h, db1h, xgA, hb + 3 * 2 * BH, hb + 1 * 2 * BH, 0, seqB);

    // final projection to vocab
    dim3 fc(NTOK / BM, V_ / BN);
    sgemm_f32x2_kernel<<<fc, 256>>>(seqB, fcW, fcb, out, NTOK, V_, H_);
}

// round 6
// speedup vs baseline: 1.0813x; 1.0813x over previous
#include <cuda_runtime.h>
#include <math.h>
#include <stdint.h>

#define B_   32
#define S_   64
#define E_   512
#define H_   1024
#define V_   32000
#define G3H  (3 * H_)
#define NTOK (B_ * S_)
#define BH   (B_ * H_)

// ---------------- scratch (device globals; no allocation allowed) ----------------
__device__ float g_ex[NTOK * E_];
__device__ float g_dx[NTOK * E_];
__device__ float g_xgA[NTOK * G3H];
__device__ float g_xgB[NTOK * G3H];
__device__ float g_seqA[NTOK * H_];
__device__ float g_seqB[NTOK * H_];
__device__ float g_h[8][BH];

// ---------------- embedding gather (with block offset so we can split launches) ----------------
__global__ void embed_kernel(const int* __restrict__ idx,
                             const float* __restrict__ emb,
                             float* __restrict__ out, int tok0) {
    int tok = tok0 + blockIdx.x;
    int row = idx[tok];
    const float4* src = (const float4*)(emb + (size_t)row * E_);
    float4* dst = (float4*)(out + (size_t)tok * E_);
    for (int i = threadIdx.x; i < E_ / 4; i += blockDim.x) dst[i] = src[i];
}

// ---------------- fp32 SGEMM: C[M,N] = A[M,K]*W[N,K]^T + bias[N] ----------------
// R1 kernel + ONE change: next-tile LDG issued before the compute block
// (latency hidden under 512 FFMAs) instead of at the top of the iteration.
// 128x128 tile, BK=8, 256 threads, 8x8 per thread, 2 CTAs/SM pinned.
#define BM 128
#define BN 128
#define BK 8

__global__ __launch_bounds__(256, 2)
void sgemm_kernel(const float* __restrict__ A,
                  const float* __restrict__ W,
                  const float* __restrict__ bias,
                  float* __restrict__ C,
                  int M, int N, int K) {
    __shared__ float As[BK][BM];
    __shared__ float Bs[BK][BN];

    const int tid = threadIdx.x;
    const int bm = blockIdx.x * BM;
    const int bn = blockIdx.y * BN;

    const int lr = tid >> 1;          // 0..127 : row within tile
    const int lk = (tid & 1) * 4;     // 0 or 4 : k quad

    const int tx = tid & 15;          // 0..15
    const int ty = tid >> 4;          // 0..15

    float acc[8][8];
#pragma unroll
    for (int i = 0; i < 8; i++)
#pragma unroll
        for (int j = 0; j < 8; j++) acc[i][j] = 0.f;

    const float* Aptr = A + (size_t)(bm + lr) * K + lk;
    const float* Wptr = W + (size_t)(bn + lr) * K + lk;

    // prefetch tile 0
    float4 av = *(const float4*)(Aptr);
    float4 bv = *(const float4*)(Wptr);

    for (int k0 = 0; k0 < K; k0 += BK) {
        __syncthreads();   // previous tile's smem reads complete
        As[lk + 0][lr] = av.x; As[lk + 1][lr] = av.y;
        As[lk + 2][lr] = av.z; As[lk + 3][lr] = av.w;
        Bs[lk + 0][lr] = bv.x; Bs[lk + 1][lr] = bv.y;
        Bs[lk + 2][lr] = bv.z; Bs[lk + 3][lr] = bv.w;
        __syncthreads();

        // issue next tile's global loads NOW; they retire under the FFMAs below
        if (k0 + BK < K) {
            av = *(const float4*)(Aptr + k0 + BK);
            bv = *(const float4*)(Wptr + k0 + BK);
        }

#pragma unroll
        for (int k = 0; k < BK; k++) {
            float a[8], b[8];
            *(float4*)&a[0] = *(const float4*)&As[k][ty * 4];
            *(float4*)&a[4] = *(const float4*)&As[k][64 + ty * 4];
            *(float4*)&b[0] = *(const float4*)&Bs[k][tx * 4];
            *(float4*)&b[4] = *(const float4*)&Bs[k][64 + tx * 4];
#pragma unroll
            for (int i = 0; i < 8; i++)
#pragma unroll
                for (int j = 0; j < 8; j++) acc[i][j] += a[i] * b[j];
        }
    }

    // epilogue: bias add + vectorized stores
#pragma unroll
    for (int i = 0; i < 8; i++) {
        int m = bm + ((i < 4) ? (ty * 4 + i) : (64 + ty * 4 + (i - 4)));
#pragma unroll
        for (int half = 0; half < 2; half++) {
            int n = bn + half * 64 + tx * 4;
            float4 bvv = *(const float4*)(bias + n);
            float4 o;
            o.x = acc[i][half * 4 + 0] + bvv.x;
            o.y = acc[i][half * 4 + 1] + bvv.y;
            o.z = acc[i][half * 4 + 2] + bvv.z;
            o.w = acc[i][half * 4 + 3] + bvv.w;
            *(float4*)(C + (size_t)m * N + n) = o;
        }
    }
}

// ---------------- fused GRU time step (body shared by single & dual) ----------------
__device__ __forceinline__ void gru_step_body(
        const float* __restrict__ h_prev,
        const float* __restrict__ Whh,
        const float* __restrict__ bhh,
        const float* __restrict__ xg,
        int t, int zero_init, int jblk,
        float* __restrict__ h_next,
        float* __restrict__ y,
        float* h_s) {
    const int tid = threadIdx.x;
    const int b = tid & 31;
    const int j = (jblk << 3) + (tid >> 5);

    float accr = bhh[j];
    float accz = bhh[H_ + j];
    float accn = bhh[2 * H_ + j];
    float h_old = 0.f;

    if (!zero_init) {
        for (int i4 = tid; i4 < BH / 4; i4 += 256) {
            int lin = i4 * 4;
            int bb = lin >> 10;
            int kk = lin & (H_ - 1);
            float4 v = *(const float4*)(h_prev + lin);
            h_s[(kk + 0) * B_ + bb] = v.x;
            h_s[(kk + 1) * B_ + bb] = v.y;
            h_s[(kk + 2) * B_ + bb] = v.z;
            h_s[(kk + 3) * B_ + bb] = v.w;
        }
        __syncthreads();

        const float* wr = Whh + (size_t)j * H_;
        const float* wz = Whh + (size_t)(H_ + j) * H_;
        const float* wn = Whh + (size_t)(2 * H_ + j) * H_;

#pragma unroll 8
        for (int k = 0; k < H_; k += 4) {
            float4 r4 = __ldg((const float4*)(wr + k));
            float4 z4 = __ldg((const float4*)(wz + k));
            float4 n4 = __ldg((const float4*)(wn + k));
            float h0 = h_s[(k + 0) * B_ + b];
            float h1 = h_s[(k + 1) * B_ + b];
            float h2 = h_s[(k + 2) * B_ + b];
            float h3 = h_s[(k + 3) * B_ + b];
            accr += h0 * r4.x + h1 * r4.y + h2 * r4.z + h3 * r4.w;
            accz += h0 * z4.x + h1 * z4.y + h2 * z4.z + h3 * z4.w;
            accn += h0 * n4.x + h1 * n4.y + h2 * n4.z + h3 * n4.w;
        }
        h_old = h_s[j * B_ + b];
    }

    const float* xp = xg + ((size_t)b * S_ + t) * G3H;
    float r = 1.f / (1.f + expf(-(xp[j] + accr)));
    float z = 1.f / (1.f + expf(-(xp[H_ + j] + accz)));
    float n = tanhf(xp[2 * H_ + j] + r * accn);
    float hnew = (1.f - z) * n + z * h_old;

    h_next[b * H_ + j] = hnew;
    if (y) y[((size_t)b * S_ + t) * H_ + j] = hnew;
}

__global__ __launch_bounds__(256)
void gru_step_kernel(const float* __restrict__ h_prev,
                     const float* __restrict__ Whh,
                     const float* __restrict__ bhh,
                     const float* __restrict__ xg,
                     int t, int zero_init,
                     float* __restrict__ h_next,
                     float* __restrict__ y) {
    extern __shared__ float h_s[];
    gru_step_body(h_prev, Whh, bhh, xg, t, zero_init, blockIdx.x, h_next, y, h_s);
}

__global__ __launch_bounds__(256)
void gru_step_dual_kernel(const float* hA, const float* WA, const float* bA,
                          const float* xA, int ziA, float* hnA, float* yA,
                          const float* hB, const float* WB, const float* bB,
                          const float* xB, int ziB, float* hnB, float* yB,
                          int t) {
    extern __shared__ float h_s[];
    if (blockIdx.x < 128)
        gru_step_body(hA, WA, bA, xA, t, ziA, blockIdx.x, hnA, yA, h_s);
    else
        gru_step_body(hB, WB, bB, xB, t, ziB, blockIdx.x - 128, hnB, yB, h_s);
}

// ---------------- driver ----------------
static void run_scan(const float* Whh, const float* bhh, const float* xg,
                     float* hpair, const float* h_init, int zero0, float* yout) {
    for (int t = 0; t < S_; t++) {
        const float* hin;
        int zi = 0;
        if (t == 0) {
            if (zero0) { hin = hpair; zi = 1; }
            else       { hin = h_init; }
        } else {
            hin = hpair + (t & 1) * BH;
        }
        float* hout = hpair + ((t + 1) & 1) * BH;
        gru_step_kernel<<<128, 256, 131072>>>(hin, Whh, bhh, xg, t, zi, hout, yout);
    }
}

extern "C" void kernel_launch(void* const* d_in, const int* in_sizes, int n_in,
                              void* d_out, int out_size) {
    const int*   enc_X   = (const int*)d_in[0];
    const int*   dec_X   = (const int*)d_in[1];
    const float* emb_enc = (const float*)d_in[2];
    const float* emb_dec = (const float*)d_in[3];
    const float* eW0i = (const float*)d_in[4];
    const float* eW0h = (const float*)d_in[5];
    const float* eb0i = (const float*)d_in[6];
    const float* eb0h = (const float*)d_in[7];
    const float* eW1i = (const float*)d_in[8];
    const float* eW1h = (const float*)d_in[9];
    const float* eb1i = (const float*)d_in[10];
    const float* eb1h = (const float*)d_in[11];
    const float* dW0i = (const float*)d_in[12];
    const float* dW0h = (const float*)d_in[13];
    const float* db0i = (const float*)d_in[14];
    const float* db0h = (const float*)d_in[15];
    const float* dW1i = (const float*)d_in[16];
    const float* dW1h = (const float*)d_in[17];
    const float* db1i = (const float*)d_in[18];
    const float* db1h = (const float*)d_in[19];
    const float* fcW  = (const float*)d_in[20];
    const float* fcb  = (const float*)d_in[21];
    float* out = (float*)d_out;

    float *ex, *dx, *xgA, *xgB, *seqA, *seqB, *hb;
    cudaGetSymbolAddress((void**)&ex,   g_ex);
    cudaGetSymbolAddress((void**)&dx,   g_dx);
    cudaGetSymbolAddress((void**)&xgA,  g_xgA);
    cudaGetSymbolAddress((void**)&xgB,  g_xgB);
    cudaGetSymbolAddress((void**)&seqA, g_seqA);
    cudaGetSymbolAddress((void**)&seqB, g_seqB);
    cudaGetSymbolAddress((void**)&hb,   g_h);

    cudaFuncSetAttribute(gru_step_kernel,
                         cudaFuncAttributeMaxDynamicSharedMemorySize, 131072);
    cudaFuncSetAttribute(gru_step_dual_kernel,
                         cudaFuncAttributeMaxDynamicSharedMemorySize, 131072);

    dim3 g3h(NTOK / BM, G3H / BN);

    // Launches 0-3: embeddings (split so launch index 5 lands on a GEMM for ncu -s 5 -c 1)
    embed_kernel<<<NTOK / 2, 128>>>(enc_X, emb_enc, ex, 0);
    embed_kernel<<<NTOK / 2, 128>>>(enc_X, emb_enc, ex, NTOK / 2);
    embed_kernel<<<NTOK / 2, 128>>>(dec_X, emb_dec, dx, 0);
    embed_kernel<<<NTOK / 2, 128>>>(dec_X, emb_dec, dx, NTOK / 2);

    // Launch 4: enc layer 0 xg. Launch 5: dec layer 0 xg (only needs dx) — PROFILED.
    sgemm_kernel<<<g3h, 256>>>(ex, eW0i, eb0i, xgA, NTOK, G3H, E_);
    sgemm_kernel<<<g3h, 256>>>(dx, dW0i, db0i, xgB, NTOK, G3H, E_);

    // encoder layer 0 scan (y0 -> seqA, final h at hb pair0 buf0)
    run_scan(eW0h, eb0h, xgA, hb + 0 * 2 * BH, nullptr, 1, seqA);

    // enc layer 1 xg (consumes seqA; xgA free again after enc0 scan)
    sgemm_kernel<<<g3h, 256>>>(seqA, eW1i, eb1i, xgA, NTOK, G3H, H_);

    // dual scan: enc layer 1 (zero init, no y) || dec layer 0 (init h_enc0, y->seqA)
    {
        float* hpA = hb + 1 * 2 * BH;
        float* hpB = hb + 2 * 2 * BH;
        const float* h0B = hb + 0 * 2 * BH;
        for (int t = 0; t < S_; t++) {
            const float* hinA; int ziA = 0;
            const float* hinB; int ziB = 0;
            if (t == 0) { hinA = hpA; ziA = 1; hinB = h0B; }
            else        { hinA = hpA + (t & 1) * BH; hinB = hpB + (t & 1) * BH; }
            float* houtA = hpA + ((t + 1) & 1) * BH;
            float* houtB = hpB + ((t + 1) & 1) * BH;
            gru_step_dual_kernel<<<256, 256, 131072>>>(
                hinA, eW1h, eb1h, xgA, ziA, houtA, nullptr,
                hinB, dW0h, db0h, xgB, ziB, houtB, seqA, t);
        }
    }

    // decoder layer 1 (init = enc layer1 final hidden), y -> seqB
    sgemm_kernel<<<g3h, 256>>>(seqA, dW1i, db1i, xgA, NTOK, G3H, H_);
    run_scan(dW1h, db1h, xgA, hb + 3 * 2 * BH, hb + 1 * 2 * BH, 0, seqB);

    // final projection to vocab
    dim3 fc(NTOK / BM, V_ / BN);
    sgemm_kernel<<<fc, 256>>>(seqB, fcW, fcb, out, NTOK, V_, H_);
}